// round 5
// baseline (speedup 1.0000x reference)
#include <cuda_runtime.h>
#include <cuda_bf16.h>
#include <math.h>
#include <stdint.h>

typedef unsigned long long ull;

// ---------------- scratch (device globals; no allocation allowed) ----------
__device__ float g_FH[8 * 256 * 1024];   // conv+bn+relu out, flat == feat_high [b][m][c]
__device__ float g_Q [8 * 4096 * 64];    // mid_low  [n][d]  (n flat over batches)
__device__ float g_Kt[8 * 64 * 1024];    // mid_high transposed [b][d][m]

// ---------------- f32x2 helpers --------------------------------------------
__device__ __forceinline__ void fma2(ull &d, ull a, ull b) {
    asm("fma.rn.f32x2 %0, %1, %2, %0;" : "+l"(d) : "l"(a), "l"(b));
}
__device__ __forceinline__ ull mul2(ull a, ull b) {
    ull r; asm("mul.rn.f32x2 %0, %1, %2;" : "=l"(r) : "l"(a), "l"(b)); return r;
}
__device__ __forceinline__ ull pk2(float x) {
    ull r; asm("mov.b64 %0, {%1, %1};" : "=l"(r) : "r"(__float_as_uint(x))); return r;
}
__device__ __forceinline__ float2 upk(ull v) {
    float2 f; asm("mov.b64 {%0, %1}, %2;" : "=f"(f.x), "=f"(f.y) : "l"(v)); return f;
}

// ---------------- cp.async helpers -----------------------------------------
__device__ __forceinline__ uint32_t cvta_s(const void* p) {
    return (uint32_t)__cvta_generic_to_shared(p);
}
__device__ __forceinline__ void cp16(uint32_t dst, const void* src) {
    asm volatile("cp.async.cg.shared.global [%0], [%1], 16;\n" :: "r"(dst), "l"(src) : "memory");
}
__device__ __forceinline__ void cp_commit() {
    asm volatile("cp.async.commit_group;\n" ::: "memory");
}

// ============================================================================
// Kernel A: 1x1 conv + BN + ReLU (unchanged from passing R2 kernel)
// ============================================================================
__global__ void __launch_bounds__(256) conv_k(
    const float* __restrict__ FHin, const float* __restrict__ Wc,
    const float* __restrict__ gam, const float* __restrict__ bet,
    const float* __restrict__ mu,  const float* __restrict__ var)
{
    __shared__ float Ws[64 * 64];
    __shared__ float Xs[64 * 128];
    const int t = threadIdx.x, tx = t & 31, ty = t >> 5;
    const int st = blockIdx.x, ot = blockIdx.y, b = blockIdx.z;
    const float* Xg = FHin + (size_t)b * 512 * 1024 + st * 128;
    const float* Wg = Wc + (size_t)ot * 64 * 512;

    ull acc[8][2];
    #pragma unroll
    for (int r = 0; r < 8; r++) { acc[r][0] = 0ull; acc[r][1] = 0ull; }

    for (int kc = 0; kc < 8; kc++) {
        __syncthreads();
        #pragma unroll
        for (int i = 0; i < 16; i++) {
            int id = i * 256 + t; int row = id >> 6, col = id & 63;
            Ws[row * 64 + col] = Wg[(size_t)row * 512 + kc * 64 + col];
        }
        #pragma unroll
        for (int i = 0; i < 8; i++) {
            int id = i * 256 + t; int row = id >> 5, c4 = id & 31;
            *(float4*)&Xs[row * 128 + c4 * 4] =
                *(const float4*)(Xg + (size_t)(kc * 64 + row) * 1024 + c4 * 4);
        }
        __syncthreads();
        #pragma unroll 8
        for (int k = 0; k < 64; k++) {
            ull x0 = *(const ull*)&Xs[k * 128 + tx * 4];
            ull x1 = *(const ull*)&Xs[k * 128 + tx * 4 + 2];
            #pragma unroll
            for (int r = 0; r < 8; r++) {
                ull wv = pk2(Ws[(ty * 8 + r) * 64 + k]);
                fma2(acc[r][0], wv, x0);
                fma2(acc[r][1], wv, x1);
            }
        }
    }
    #pragma unroll
    for (int r = 0; r < 8; r++) {
        int o = ot * 64 + ty * 8 + r;
        float inv = gam[o] * rsqrtf(var[o] + 1e-5f);
        float bs  = bet[o] - mu[o] * inv;
        float2 a = upk(acc[r][0]), c2 = upk(acc[r][1]);
        float4 v;
        v.x = fmaxf(fmaf(a.x,  inv, bs), 0.f);
        v.y = fmaxf(fmaf(a.y,  inv, bs), 0.f);
        v.z = fmaxf(fmaf(c2.x, inv, bs), 0.f);
        v.w = fmaxf(fmaf(c2.y, inv, bs), 0.f);
        *(float4*)&g_FH[((size_t)b * 256 + o) * 1024 + st * 128 + tx * 4] = v;
    }
}

// ============================================================================
// Kernel B/C: fc GEMM (unchanged from passing R2 kernel)
// ============================================================================
template<bool TRANSC>
__global__ void __launch_bounds__(256) fc_k(
    const float* __restrict__ Xin, const float* __restrict__ W,
    const float* __restrict__ bias)
{
    __shared__ float Xs[128 * 64];
    __shared__ float Ws[64 * 66];
    const int t = threadIdx.x, tx = t & 15, ty = t >> 4;
    const int n0 = blockIdx.x * 128;
    const float* X = TRANSC ? (const float*)g_FH : Xin;

    ull acc[8][2];
    #pragma unroll
    for (int r = 0; r < 8; r++) { acc[r][0] = 0ull; acc[r][1] = 0ull; }

    for (int kc = 0; kc < 4; kc++) {
        __syncthreads();
        #pragma unroll
        for (int i = 0; i < 8; i++) {
            int id = i * 256 + t; int row = id >> 4, c4 = id & 15;
            *(float4*)&Xs[row * 64 + c4 * 4] =
                *(const float4*)(X + (size_t)(n0 + row) * 256 + kc * 64 + c4 * 4);
        }
        #pragma unroll
        for (int i = 0; i < 16; i++) {
            int id = i * 256 + t; int d = id >> 6, c = id & 63;
            Ws[c * 66 + d] = W[(size_t)d * 256 + kc * 64 + c];
        }
        __syncthreads();
        #pragma unroll 8
        for (int c = 0; c < 64; c++) {
            ull w0 = *(const ull*)&Ws[c * 66 + tx * 4];
            ull w1 = *(const ull*)&Ws[c * 66 + tx * 4 + 2];
            #pragma unroll
            for (int r = 0; r < 8; r++) {
                ull xv = pk2(Xs[(ty * 8 + r) * 64 + c]);
                fma2(acc[r][0], xv, w0);
                fma2(acc[r][1], xv, w1);
            }
        }
    }
    if (!TRANSC) {
        float4 bv = *(const float4*)(bias + tx * 4);
        #pragma unroll
        for (int r = 0; r < 8; r++) {
            float2 a = upk(acc[r][0]), c2 = upk(acc[r][1]);
            float4 v = make_float4(a.x + bv.x, a.y + bv.y, c2.x + bv.z, c2.y + bv.w);
            *(float4*)&g_Q[(size_t)(n0 + ty * 8 + r) * 64 + tx * 4] = v;
        }
    } else {
        float4 bv = *(const float4*)(bias + tx * 4);
        #pragma unroll
        for (int r = 0; r < 8; r++) {
            int n = n0 + ty * 8 + r;
            int bb = n >> 10, m = n & 1023;
            float2 a = upk(acc[r][0]), c2 = upk(acc[r][1]);
            g_Kt[((size_t)bb * 64 + tx * 4 + 0) * 1024 + m] = a.x  + bv.x;
            g_Kt[((size_t)bb * 64 + tx * 4 + 1) * 1024 + m] = a.y  + bv.y;
            g_Kt[((size_t)bb * 64 + tx * 4 + 2) * 1024 + m] = c2.x + bv.z;
            g_Kt[((size_t)bb * 64 + tx * 4 + 3) * 1024 + m] = c2.y + bv.w;
        }
    }
}

// ============================================================================
// Kernel D: fused attention, restructured for 4x lower smem traffic.
// Block = 64 Q-rows of one batch, 512 threads = 16 warps = 4 rowgroups x 4 colslabs.
// Warp (g,s): S sub-tile 16 rows x 16 m;  PV slab 16 rows x 64 cols.
// S -> smem -> softmax (redundant per slab, warp-local rows) -> PV.
// smem floats: Q 64x68 | Kt 2x(64x64) | FH 2x(64x260) | S 64x68 | P 64x68
// ============================================================================
#define FH_STRIDE 260
#define FH_BUF    16640
#define KT_BUF    4096
#define QS_STRIDE 68

__device__ __forceinline__ void issue_tile(int t, int mt, int buf,
    uint32_t Ktsa, uint32_t FHsa, const float* Ktg, const float* FHg)
{
    const float* ks = Ktg + mt * 64;
    #pragma unroll
    for (int i = 0; i < 2; i++) {
        int id = i * 512 + t; int d = id >> 4, ch = id & 15;
        cp16(Ktsa + (uint32_t)(buf * KT_BUF + d * 64 + ch * 4) * 4,
             ks + (size_t)d * 1024 + ch * 4);
    }
    const float* fs = FHg + (size_t)mt * 64 * 256;
    #pragma unroll
    for (int i = 0; i < 8; i++) {
        int id = i * 512 + t; int row = id >> 6, ch = id & 63;
        cp16(FHsa + (uint32_t)(buf * FH_BUF + row * FH_STRIDE + ch * 4) * 4,
             fs + (size_t)row * 256 + ch * 4);
    }
}

__global__ void __launch_bounds__(512, 1) attn_k(
    const float* __restrict__ scp, float* __restrict__ out)
{
    extern __shared__ float sm[];
    float* Q_s  = sm;                  // 64*68   = 4352
    float* Kt_s = sm + 4352;           // 2*4096  = 8192
    float* FH_s = sm + 12544;          // 2*16640 = 33280
    float* S_s  = sm + 45824;          // 64*68   = 4352
    float* P_s  = sm + 50176;          // 64*68   = 4352   (total 54528 fl)

    const int b = blockIdx.y, nblk = blockIdx.x;
    const int t = threadIdx.x, w = t >> 5, l = t & 31;
    const int g = w >> 2, sl = w & 3;          // rowgroup / colslab
    const int riS = l >> 2, cpS = l & 3;       // S-phase lane map
    const int ri  = l >> 3, ci  = l & 7;       // softmax/PV lane map

    const float* Qg  = g_Q  + ((size_t)b * 4096 + nblk * 64) * 64;
    const float* Ktg = g_Kt + (size_t)b * 64 * 1024;
    const float* FHg = g_FH + (size_t)b * 1024 * 256;

    uint32_t Qsa  = cvta_s(Q_s);
    uint32_t Ktsa = cvta_s(Kt_s);
    uint32_t FHsa = cvta_s(FH_s);

    // prologue: Q tile (stride 68) + m-tile 0
    #pragma unroll
    for (int i = 0; i < 2; i++) {
        int id = i * 512 + t; int row = id >> 4, ch = id & 15;
        cp16(Qsa + (uint32_t)(row * QS_STRIDE + ch * 4) * 4, Qg + (size_t)row * 64 + ch * 4);
    }
    issue_tile(t, 0, 0, Ktsa, FHsa, Ktg, FHg);
    cp_commit();

    ull oacc[4][4];
    #pragma unroll
    for (int k = 0; k < 4; k++)
        #pragma unroll
        for (int j = 0; j < 4; j++) oacc[k][j] = 0ull;
    float mrun[4] = {-INFINITY, -INFINITY, -INFINITY, -INFINITY};
    float lrun[4] = {0.f, 0.f, 0.f, 0.f};

    // pointers fixed per thread
    const float* q0p = Q_s + (16 * g + riS) * QS_STRIDE;
    const float* q1p = Q_s + (16 * g + 8 + riS) * QS_STRIDE;
    float* sp0 = S_s + (16 * g + riS) * QS_STRIDE + 16 * sl + cpS * 4;
    float* sp1 = S_s + (16 * g + 8 + riS) * QS_STRIDE + 16 * sl + cpS * 4;

    for (int tb = 0; tb < 16; tb++) {
        if (tb < 15) {
            issue_tile(t, tb + 1, (tb + 1) & 1, Ktsa, FHsa, Ktg, FHg);
            cp_commit();
            asm volatile("cp.async.wait_group 1;\n" ::: "memory");
        } else {
            asm volatile("cp.async.wait_group 0;\n" ::: "memory");
        }
        __syncthreads();

        const float* KtB = Kt_s + (tb & 1) * KT_BUF;
        const float* FHB = FH_s + (tb & 1) * FH_BUF;

        // ---- S: warp (g,sl) computes 16 rows x 16 m; thread: 2 rows x 4 m ----
        {
            ull s00 = 0ull, s01 = 0ull, s10 = 0ull, s11 = 0ull;
            const float* ktp = KtB + 16 * sl + cpS * 4;
            #pragma unroll 8
            for (int d = 0; d < 64; d++) {
                ulonglong2 kt = *(const ulonglong2*)(ktp + d * 64);
                ull q0 = pk2(q0p[d]);
                ull q1 = pk2(q1p[d]);
                fma2(s00, q0, kt.x); fma2(s01, q0, kt.y);
                fma2(s10, q1, kt.x); fma2(s11, q1, kt.y);
            }
            *(ull*)sp0 = s00; *(ull*)(sp0 + 2) = s01;
            *(ull*)sp1 = s10; *(ull*)(sp1 + 2) = s11;
        }
        __syncthreads();

        // ---- softmax: all 4 slab-warps of group g compute (identical),
        //      only sl==0 stores P. Lane owns rows 16g+ri+4k, m-octet ci*8. ----
        #pragma unroll
        for (int k = 0; k < 4; k++) {
            int row = 16 * g + ri + 4 * k;
            const float* srow = S_s + row * QS_STRIDE + ci * 8;
            float4 a  = *(const float4*)srow;
            float4 b4 = *(const float4*)(srow + 4);
            float mt_ = fmaxf(fmaxf(fmaxf(a.x, a.y), fmaxf(a.z, a.w)),
                              fmaxf(fmaxf(b4.x, b4.y), fmaxf(b4.z, b4.w)));
            mt_ = fmaxf(mt_, __shfl_xor_sync(0xffffffffu, mt_, 1));
            mt_ = fmaxf(mt_, __shfl_xor_sync(0xffffffffu, mt_, 2));
            mt_ = fmaxf(mt_, __shfl_xor_sync(0xffffffffu, mt_, 4));
            float mnew  = fmaxf(mrun[k], mt_);
            float alpha = __expf(mrun[k] - mnew);
            float e0 = __expf(a.x  - mnew), e1 = __expf(a.y  - mnew);
            float e2 = __expf(a.z  - mnew), e3 = __expf(a.w  - mnew);
            float e4 = __expf(b4.x - mnew), e5 = __expf(b4.y - mnew);
            float e6 = __expf(b4.z - mnew), e7 = __expf(b4.w - mnew);
            float ps = ((e0 + e1) + (e2 + e3)) + ((e4 + e5) + (e6 + e7));
            ps += __shfl_xor_sync(0xffffffffu, ps, 1);
            ps += __shfl_xor_sync(0xffffffffu, ps, 2);
            ps += __shfl_xor_sync(0xffffffffu, ps, 4);
            lrun[k] = lrun[k] * alpha + ps;
            mrun[k] = mnew;
            ull a2 = pk2(alpha);
            oacc[k][0] = mul2(oacc[k][0], a2);
            oacc[k][1] = mul2(oacc[k][1], a2);
            oacc[k][2] = mul2(oacc[k][2], a2);
            oacc[k][3] = mul2(oacc[k][3], a2);
            if (sl == 0) {
                float* prow = P_s + row * QS_STRIDE + ci * 8;
                *(float4*)prow       = make_float4(e0, e1, e2, e3);
                *(float4*)(prow + 4) = make_float4(e4, e5, e6, e7);
            }
        }
        __syncthreads();

        // ---- PV: warp slab 16 rows x 64 cols; thread 4 rows x 8 cols ----
        {
            const float* fhp = FHB + 64 * sl + ci * 8;
            const float* pr0 = P_s + (16 * g + ri) * QS_STRIDE;
            #pragma unroll 4
            for (int m = 0; m < 64; m += 2) {
                ulonglong2 fa0 = *(const ulonglong2*)(fhp + m * FH_STRIDE);
                ulonglong2 fa1 = *(const ulonglong2*)(fhp + m * FH_STRIDE + 4);
                ulonglong2 fb0 = *(const ulonglong2*)(fhp + (m + 1) * FH_STRIDE);
                ulonglong2 fb1 = *(const ulonglong2*)(fhp + (m + 1) * FH_STRIDE + 4);
                #pragma unroll
                for (int k = 0; k < 4; k++) {
                    float2 pv = *(const float2*)(pr0 + k * 4 * QS_STRIDE + m);
                    ull p0 = pk2(pv.x), p1 = pk2(pv.y);
                    fma2(oacc[k][0], p0, fa0.x); fma2(oacc[k][1], p0, fa0.y);
                    fma2(oacc[k][2], p0, fa1.x); fma2(oacc[k][3], p0, fa1.y);
                    fma2(oacc[k][0], p1, fb0.x); fma2(oacc[k][1], p1, fb0.y);
                    fma2(oacc[k][2], p1, fb1.x); fma2(oacc[k][3], p1, fb1.y);
                }
            }
        }
        __syncthreads();
    }

    // ---- epilogue: O[n][c] * scale / l -> out[b][c][n] via smem transpose ----
    float sc = scp[0];
    float* O_s = FH_s;  // stride 257, scalar writes (odd stride -> no conflicts)
    #pragma unroll
    for (int k = 0; k < 4; k++) {
        float inv = sc / lrun[k];
        int row = 16 * g + ri + 4 * k;
        #pragma unroll
        for (int j = 0; j < 4; j++) {
            float2 v = upk(oacc[k][j]);
            O_s[row * 257 + 64 * sl + ci * 8 + 2 * j]     = v.x * inv;
            O_s[row * 257 + 64 * sl + ci * 8 + 2 * j + 1] = v.y * inv;
        }
    }
    __syncthreads();
    float* outB = out + (size_t)b * 256 * 4096 + nblk * 64;
    #pragma unroll
    for (int j = 0; j < 8; j++) {
        int c  = j * 32 + (t >> 4);
        int nn = (t & 15) * 4;
        float4 v;
        v.x = O_s[(nn + 0) * 257 + c];
        v.y = O_s[(nn + 1) * 257 + c];
        v.z = O_s[(nn + 2) * 257 + c];
        v.w = O_s[(nn + 3) * 257 + c];
        *(float4*)(outB + (size_t)c * 4096 + nn) = v;
    }
}

// ============================================================================
extern "C" void kernel_launch(void* const* d_in, const int* in_sizes, int n_in,
                              void* d_out, int out_size)
{
    const float* fms_low  = (const float*)d_in[0];
    const float* fms_high = (const float*)d_in[1];
    const float* w_conv   = (const float*)d_in[2];
    const float* gam      = (const float*)d_in[3];
    const float* bet      = (const float*)d_in[4];
    const float* mu       = (const float*)d_in[5];
    const float* var      = (const float*)d_in[6];
    const float* fc1w     = (const float*)d_in[7];
    const float* fc1b     = (const float*)d_in[8];
    const float* fc2w     = (const float*)d_in[9];
    const float* fc2b     = (const float*)d_in[10];
    const float* scale    = (const float*)d_in[11];
    float* out = (float*)d_out;

    conv_k<<<dim3(8, 4, 8), 256>>>(fms_high, w_conv, gam, bet, mu, var);
    fc_k<false><<<256, 256>>>(fms_low, fc1w, fc1b);
    fc_k<true ><<<64,  256>>>(nullptr,  fc2w, fc2b);

    cudaFuncSetAttribute(attn_k, cudaFuncAttributeMaxDynamicSharedMemorySize, 218112);
    attn_k<<<dim3(64, 8), 512, 218112>>>(scale, out);
}

// round 8
// speedup vs baseline: 1.0002x; 1.0002x over previous
#include <cuda_runtime.h>
#include <cuda_bf16.h>
#include <math.h>
#include <stdint.h>

typedef unsigned long long ull;

__device__ float g_FH[8 * 256 * 1024];
__device__ float g_Q [8 * 4096 * 64];
__device__ float g_Kt[8 * 64 * 1024];

__device__ __forceinline__ void fma2(ull &d, ull a, ull b) {
    asm("fma.rn.f32x2 %0, %1, %2, %0;" : "+l"(d) : "l"(a), "l"(b));
}
__device__ __forceinline__ ull mul2(ull a, ull b) {
    ull r; asm("mul.rn.f32x2 %0, %1, %2;" : "=l"(r) : "l"(a), "l"(b)); return r;
}
__device__ __forceinline__ ull pk2(float x) {
    ull r; asm("mov.b64 %0, {%1, %1};" : "=l"(r) : "r"(__float_as_uint(x))); return r;
}
__device__ __forceinline__ float2 upk(ull v) {
    float2 f; asm("mov.b64 {%0, %1}, %2;" : "=f"(f.x), "=f"(f.y) : "l"(v)); return f;
}
__device__ __forceinline__ uint32_t cvta_s(const void* p) {
    return (uint32_t)__cvta_generic_to_shared(p);
}
__device__ __forceinline__ void cp16(uint32_t dst, const void* src) {
    asm volatile("cp.async.cg.shared.global [%0], [%1], 16;\n" :: "r"(dst), "l"(src) : "memory");
}
__device__ __forceinline__ void cp_commit() {
    asm volatile("cp.async.commit_group;\n" ::: "memory");
}

__global__ void __launch_bounds__(256) conv_k(
    const float* __restrict__ FHin, const float* __restrict__ Wc,
    const float* __restrict__ gam, const float* __restrict__ bet,
    const float* __restrict__ mu,  const float* __restrict__ var)
{
    __shared__ float Ws[64 * 64];
    __shared__ float Xs[64 * 128];
    const int t = threadIdx.x, tx = t & 31, ty = t >> 5;
    const int st = blockIdx.x, ot = blockIdx.y, b = blockIdx.z;
    const float* Xg = FHin + (size_t)b * 512 * 1024 + st * 128;
    const float* Wg = Wc + (size_t)ot * 64 * 512;

    ull acc[8][2];
    #pragma unroll
    for (int r = 0; r < 8; r++) { acc[r][0] = 0ull; acc[r][1] = 0ull; }

    for (int kc = 0; kc < 8; kc++) {
        __syncthreads();
        #pragma unroll
        for (int i = 0; i < 16; i++) {
            int id = i * 256 + t; int row = id >> 6, col = id & 63;
            Ws[row * 64 + col] = Wg[(size_t)row * 512 + kc * 64 + col];
        }
        #pragma unroll
        for (int i = 0; i < 8; i++) {
            int id = i * 256 + t; int row = id >> 5, c4 = id & 31;
            *(float4*)&Xs[row * 128 + c4 * 4] =
                *(const float4*)(Xg + (size_t)(kc * 64 + row) * 1024 + c4 * 4);
        }
        __syncthreads();
        #pragma unroll 8
        for (int k = 0; k < 64; k++) {
            ull x0 = *(const ull*)&Xs[k * 128 + tx * 4];
            ull x1 = *(const ull*)&Xs[k * 128 + tx * 4 + 2];
            #pragma unroll
            for (int r = 0; r < 8; r++) {
                ull wv = pk2(Ws[(ty * 8 + r) * 64 + k]);
                fma2(acc[r][0], wv, x0);
                fma2(acc[r][1], wv, x1);
            }
        }
    }
    #pragma unroll
    for (int r = 0; r < 8; r++) {
        int o = ot * 64 + ty * 8 + r;
        float inv = gam[o] * rsqrtf(var[o] + 1e-5f);
        float bs  = bet[o] - mu[o] * inv;
        float2 a = upk(acc[r][0]), c2 = upk(acc[r][1]);
        float4 v;
        v.x = fmaxf(fmaf(a.x,  inv, bs), 0.f);
        v.y = fmaxf(fmaf(a.y,  inv, bs), 0.f);
        v.z = fmaxf(fmaf(c2.x, inv, bs), 0.f);
        v.w = fmaxf(fmaf(c2.y, inv, bs), 0.f);
        *(float4*)&g_FH[((size_t)b * 256 + o) * 1024 + st * 128 + tx * 4] = v;
    }
}

template<bool TRANSC>
__global__ void __launch_bounds__(256) fc_k(
    const float* __restrict__ Xin, const float* __restrict__ W,
    const float* __restrict__ bias)
{
    __shared__ float Xs[128 * 64];
    __shared__ float Ws[64 * 66];
    const int t = threadIdx.x, tx = t & 15, ty = t >> 4;
    const int n0 = blockIdx.x * 128;
    const float* X = TRANSC ? (const float*)g_FH : Xin;

    ull acc[8][2];
    #pragma unroll
    for (int r = 0; r < 8; r++) { acc[r][0] = 0ull; acc[r][1] = 0ull; }

    for (int kc = 0; kc < 4; kc++) {
        __syncthreads();
        #pragma unroll
        for (int i = 0; i < 8; i++) {
            int id = i * 256 + t; int row = id >> 4, c4 = id & 15;
            *(float4*)&Xs[row * 64 + c4 * 4] =
                *(const float4*)(X + (size_t)(n0 + row) * 256 + kc * 64 + c4 * 4);
        }
        #pragma unroll
        for (int i = 0; i < 16; i++) {
            int id = i * 256 + t; int d = id >> 6, c = id & 63;
            Ws[c * 66 + d] = W[(size_t)d * 256 + kc * 64 + c];
        }
        __syncthreads();
        #pragma unroll 8
        for (int c = 0; c < 64; c++) {
            ull w0 = *(const ull*)&Ws[c * 66 + tx * 4];
            ull w1 = *(const ull*)&Ws[c * 66 + tx * 4 + 2];
            #pragma unroll
            for (int r = 0; r < 8; r++) {
                ull xv = pk2(Xs[(ty * 8 + r) * 64 + c]);
                fma2(acc[r][0], xv, w0);
                fma2(acc[r][1], xv, w1);
            }
        }
    }
    if (!TRANSC) {
        float4 bv = *(const float4*)(bias + tx * 4);
        #pragma unroll
        for (int r = 0; r < 8; r++) {
            float2 a = upk(acc[r][0]), c2 = upk(acc[r][1]);
            float4 v = make_float4(a.x + bv.x, a.y + bv.y, c2.x + bv.z, c2.y + bv.w);
            *(float4*)&g_Q[(size_t)(n0 + ty * 8 + r) * 64 + tx * 4] = v;
        }
    } else {
        float4 bv = *(const float4*)(bias + tx * 4);
        #pragma unroll
        for (int r = 0; r < 8; r++) {
            int n = n0 + ty * 8 + r;
            int bb = n >> 10, m = n & 1023;
            float2 a = upk(acc[r][0]), c2 = upk(acc[r][1]);
            g_Kt[((size_t)bb * 64 + tx * 4 + 0) * 1024 + m] = a.x  + bv.x;
            g_Kt[((size_t)bb * 64 + tx * 4 + 1) * 1024 + m] = a.y  + bv.y;
            g_Kt[((size_t)bb * 64 + tx * 4 + 2) * 1024 + m] = c2.x + bv.z;
            g_Kt[((size_t)bb * 64 + tx * 4 + 3) * 1024 + m] = c2.y + bv.w;
        }
    }
}

#define FH_STRIDE 260
#define FH_BUF    16640
#define KT_BUF    4096
#define QS_STRIDE 68

__device__ __forceinline__ void issue_tile(int t, int mt, int buf,
    uint32_t Ktsa, uint32_t FHsa, const float* Ktg, const float* FHg)
{
    const float* ks = Ktg + mt * 64;
    #pragma unroll
    for (int i = 0; i < 2; i++) {
        int id = i * 512 + t; int d = id >> 4, ch = id & 15;
        cp16(Ktsa + (uint32_t)(buf * KT_BUF + d * 64 + ch * 4) * 4,
             ks + (size_t)d * 1024 + ch * 4);
    }
    const float* fs = FHg + (size_t)mt * 64 * 256;
    #pragma unroll
    for (int i = 0; i < 8; i++) {
        int id = i * 512 + t; int row = id >> 6, ch = id & 63;
        cp16(FHsa + (uint32_t)(buf * FH_BUF + row * FH_STRIDE + ch * 4) * 4,
             fs + (size_t)row * 256 + ch * 4);
    }
}

__global__ void __launch_bounds__(512, 1) attn_k(
    const float* __restrict__ scp, float* __restrict__ out)
{
    extern __shared__ float sm[];
    float* Q_s  = sm;
    float* Kt_s = sm + 4352;
    float* FH_s = sm + 12544;
    float* S_s  = sm + 45824;
    float* P_s  = sm + 50176;

    const int b = blockIdx.y, nblk = blockIdx.x;
    const int t = threadIdx.x, w = t >> 5, l = t & 31;
    const int g = w >> 2, sl = w & 3;
    const int riS = l >> 2, cpS = l & 3;
    const int ri  = l >> 3, ci  = l & 7;

    const float* Qg  = g_Q  + ((size_t)b * 4096 + nblk * 64) * 64;
    const float* Ktg = g_Kt + (size_t)b * 64 * 1024;
    const float* FHg = g_FH + (size_t)b * 1024 * 256;

    uint32_t Qsa  = cvta_s(Q_s);
    uint32_t Ktsa = cvta_s(Kt_s);
    uint32_t FHsa = cvta_s(FH_s);

    #pragma unroll
    for (int i = 0; i < 2; i++) {
        int id = i * 512 + t; int row = id >> 4, ch = id & 15;
        cp16(Qsa + (uint32_t)(row * QS_STRIDE + ch * 4) * 4, Qg + (size_t)row * 64 + ch * 4);
    }
    issue_tile(t, 0, 0, Ktsa, FHsa, Ktg, FHg);
    cp_commit();

    ull oacc[4][4];
    #pragma unroll
    for (int k = 0; k < 4; k++)
        #pragma unroll
        for (int j = 0; j < 4; j++) oacc[k][j] = 0ull;
    float mrun[4] = {-INFINITY, -INFINITY, -INFINITY, -INFINITY};
    float lrun[4] = {0.f, 0.f, 0.f, 0.f};

    const float* q0p = Q_s + (16 * g + riS) * QS_STRIDE;
    const float* q1p = Q_s + (16 * g + 8 + riS) * QS_STRIDE;
    float* sp0 = S_s + (16 * g + riS) * QS_STRIDE + 16 * sl + cpS * 4;
    float* sp1 = S_s + (16 * g + 8 + riS) * QS_STRIDE + 16 * sl + cpS * 4;

    for (int tb = 0; tb < 16; tb++) {
        if (tb < 15) {
            issue_tile(t, tb + 1, (tb + 1) & 1, Ktsa, FHsa, Ktg, FHg);
            cp_commit();
            asm volatile("cp.async.wait_group 1;\n" ::: "memory");
        } else {
            asm volatile("cp.async.wait_group 0;\n" ::: "memory");
        }
        __syncthreads();

        const float* KtB = Kt_s + (tb & 1) * KT_BUF;
        const float* FHB = FH_s + (tb & 1) * FH_BUF;

        // S = Q.K^T  (narrow LDS.64 K loads)
        {
            ull s00 = 0ull, s01 = 0ull, s10 = 0ull, s11 = 0ull;
            const float* ktp = KtB + 16 * sl + cpS * 4;
            #pragma unroll 8
            for (int d = 0; d < 64; d++) {
                ull ktx = *(const ull*)(ktp + d * 64);
                ull kty = *(const ull*)(ktp + d * 64 + 2);
                ull q0 = pk2(q0p[d]);
                ull q1 = pk2(q1p[d]);
                fma2(s00, q0, ktx); fma2(s01, q0, kty);
                fma2(s10, q1, ktx); fma2(s11, q1, kty);
            }
            *(ull*)sp0 = s00; *(ull*)(sp0 + 2) = s01;
            *(ull*)sp1 = s10; *(ull*)(sp1 + 2) = s11;
        }
        __syncthreads();

        // softmax (redundant per slab; only sl==0 stores P)
        #pragma unroll
        for (int k = 0; k < 4; k++) {
            int row = 16 * g + ri + 4 * k;
            const float* srow = S_s + row * QS_STRIDE + ci * 8;
            float4 a  = *(const float4*)srow;
            float4 b4 = *(const float4*)(srow + 4);
            float mt_ = fmaxf(fmaxf(fmaxf(a.x, a.y), fmaxf(a.z, a.w)),
                              fmaxf(fmaxf(b4.x, b4.y), fmaxf(b4.z, b4.w)));
            mt_ = fmaxf(mt_, __shfl_xor_sync(0xffffffffu, mt_, 1));
            mt_ = fmaxf(mt_, __shfl_xor_sync(0xffffffffu, mt_, 2));
            mt_ = fmaxf(mt_, __shfl_xor_sync(0xffffffffu, mt_, 4));
            float mnew  = fmaxf(mrun[k], mt_);
            float alpha = __expf(mrun[k] - mnew);
            float e0 = __expf(a.x  - mnew), e1 = __expf(a.y  - mnew);
            float e2 = __expf(a.z  - mnew), e3 = __expf(a.w  - mnew);
            float e4 = __expf(b4.x - mnew), e5 = __expf(b4.y - mnew);
            float e6 = __expf(b4.z - mnew), e7 = __expf(b4.w - mnew);
            float ps = ((e0 + e1) + (e2 + e3)) + ((e4 + e5) + (e6 + e7));
            ps += __shfl_xor_sync(0xffffffffu, ps, 1);
            ps += __shfl_xor_sync(0xffffffffu, ps, 2);
            ps += __shfl_xor_sync(0xffffffffu, ps, 4);
            lrun[k] = lrun[k] * alpha + ps;
            mrun[k] = mnew;
            ull a2 = pk2(alpha);
            oacc[k][0] = mul2(oacc[k][0], a2);
            oacc[k][1] = mul2(oacc[k][1], a2);
            oacc[k][2] = mul2(oacc[k][2], a2);
            oacc[k][3] = mul2(oacc[k][3], a2);
            if (sl == 0) {
                float* prow = P_s + row * QS_STRIDE + ci * 8;
                *(float4*)prow       = make_float4(e0, e1, e2, e3);
                *(float4*)(prow + 4) = make_float4(e4, e5, e6, e7);
            }
        }
        __syncthreads();   // cross-warp P visibility (was __syncwarp)

        // PV (narrow LDS.64 FH loads)
        {
            const float* fhp = FHB + 64 * sl + ci * 8;
            const float* pr0 = P_s + (16 * g + ri) * QS_STRIDE;
            #pragma unroll 4
            for (int m = 0; m < 64; m += 2) {
                const float* fra = fhp + m * FH_STRIDE;
                const float* frb = fhp + (m + 1) * FH_STRIDE;
                ull fa0 = *(const ull*)(fra + 0);
                ull fa1 = *(const ull*)(fra + 2);
                ull fa2 = *(const ull*)(fra + 4);
                ull fa3 = *(const ull*)(fra + 6);
                ull fb0 = *(const ull*)(frb + 0);
                ull fb1 = *(const ull*)(frb + 2);
                ull fb2 = *(const ull*)(frb + 4);
                ull fb3 = *(const ull*)(frb + 6);
                #pragma unroll
                for (int k = 0; k < 4; k++) {
                    float2 pv = *(const float2*)(pr0 + k * 4 * QS_STRIDE + m);
                    ull p0 = pk2(pv.x), p1 = pk2(pv.y);
                    fma2(oacc[k][0], p0, fa0); fma2(oacc[k][1], p0, fa1);
                    fma2(oacc[k][2], p0, fa2); fma2(oacc[k][3], p0, fa3);
                    fma2(oacc[k][0], p1, fb0); fma2(oacc[k][1], p1, fb1);
                    fma2(oacc[k][2], p1, fb2); fma2(oacc[k][3], p1, fb3);
                }
            }
        }
        __syncthreads();
    }

    float sc = scp[0];
    float* O_s = FH_s;
    #pragma unroll
    for (int k = 0; k < 4; k++) {
        float inv = sc / lrun[k];
        int row = 16 * g + ri + 4 * k;
        #pragma unroll
        for (int j = 0; j < 4; j++) {
            float2 v = upk(oacc[k][j]);
            O_s[row * 257 + 64 * sl + ci * 8 + 2 * j]     = v.x * inv;
            O_s[row * 257 + 64 * sl + ci * 8 + 2 * j + 1] = v.y * inv;
        }
    }
    __syncthreads();
    float* outB = out + (size_t)b * 256 * 4096 + nblk * 64;
    #pragma unroll
    for (int j = 0; j < 8; j++) {
        int c  = j * 32 + (t >> 4);
        int nn = (t & 15) * 4;
        float4 v;
        v.x = O_s[(nn + 0) * 257 + c];
        v.y = O_s[(nn + 1) * 257 + c];
        v.z = O_s[(nn + 2) * 257 + c];
        v.w = O_s[(nn + 3) * 257 + c];
        *(float4*)(outB + (size_t)c * 4096 + nn) = v;
    }
}

extern "C" void kernel_launch(void* const* d_in, const int* in_sizes, int n_in,
                              void* d_out, int out_size)
{
    const float* fms_high = (const float*)d_in[1];
    const float* w_conv   = (const float*)d_in[2];
    const float* gam      = (const float*)d_in[3];
    const float* bet      = (const float*)d_in[4];
    const float* mu       = (const float*)d_in[5];
    const float* var      = (const float*)d_in[6];
    float* out = (float*)d_out;

    conv_k<<<dim3(8, 4, 8), 256>>>(fms_high, w_conv, gam, bet, mu, var);
    fc_k<false><<<256, 256>>>((const float*)d_in[0], (const float*)d_in[7], (const float*)d_in[8]);
    fc_k<true ><<<64,  256>>>(nullptr, (const float*)d_in[9], (const float*)d_in[10]);

    cudaFuncSetAttribute(attn_k, cudaFuncAttributeMaxDynamicSharedMemorySize, 218112);
    attn_k<<<dim3(64, 8), 512, 218112>>>((const float*)d_in[11], out);
}

// round 10
// speedup vs baseline: 1.4269x; 1.4266x over previous
#include <cuda_runtime.h>
#include <math.h>
#include <stdint.h>

typedef unsigned long long ull;

__device__ float g_FH[8 * 1024 * 256];   // [b][m][c] (flat reshape of conv out)
__device__ float g_Qt[8 * 64 * 4096];    // [b][d][n]
__device__ float g_Kt[8 * 64 * 1024];    // [b][d][m]

__device__ __forceinline__ void fma2(ull &d, ull a, ull b) {
    asm("fma.rn.f32x2 %0, %1, %2, %0;" : "+l"(d) : "l"(a), "l"(b));
}
__device__ __forceinline__ ull mul2(ull a, ull b) {
    ull r; asm("mul.rn.f32x2 %0, %1, %2;" : "=l"(r) : "l"(a), "l"(b)); return r;
}
__device__ __forceinline__ ull pk2(float x) {
    ull r; asm("mov.b64 %0, {%1, %1};" : "=l"(r) : "r"(__float_as_uint(x))); return r;
}
__device__ __forceinline__ float2 upk(ull v) {
    float2 f; asm("mov.b64 {%0, %1}, %2;" : "=f"(f.x), "=f"(f.y) : "l"(v)); return f;
}
__device__ __forceinline__ uint32_t cvta_s(const void* p) {
    return (uint32_t)__cvta_generic_to_shared(p);
}
__device__ __forceinline__ void cp16(uint32_t dst, const void* src) {
    asm volatile("cp.async.cg.shared.global [%0], [%1], 16;\n" :: "r"(dst), "l"(src) : "memory");
}
__device__ __forceinline__ void cp_commit() {
    asm volatile("cp.async.commit_group;\n" ::: "memory");
}
template<int N> __device__ __forceinline__ void cp_wait() {
    asm volatile("cp.async.wait_group %0;\n" :: "n"(N) : "memory");
}

// ======================= conv+BN+ReLU (proven) =============================
__global__ void __launch_bounds__(256) conv_k(
    const float* __restrict__ FHin, const float* __restrict__ Wc,
    const float* __restrict__ gam, const float* __restrict__ bet,
    const float* __restrict__ mu,  const float* __restrict__ var)
{
    __shared__ float Ws[64 * 64];
    __shared__ float Xs[64 * 128];
    const int t = threadIdx.x, tx = t & 31, ty = t >> 5;
    const int st = blockIdx.x, ot = blockIdx.y, b = blockIdx.z;
    const float* Xg = FHin + (size_t)b * 512 * 1024 + st * 128;
    const float* Wg = Wc + (size_t)ot * 64 * 512;

    ull acc[8][2];
    #pragma unroll
    for (int r = 0; r < 8; r++) { acc[r][0] = 0ull; acc[r][1] = 0ull; }

    for (int kc = 0; kc < 8; kc++) {
        __syncthreads();
        #pragma unroll
        for (int i = 0; i < 16; i++) {
            int id = i * 256 + t; int row = id >> 6, col = id & 63;
            Ws[row * 64 + col] = Wg[(size_t)row * 512 + kc * 64 + col];
        }
        #pragma unroll
        for (int i = 0; i < 8; i++) {
            int id = i * 256 + t; int row = id >> 5, c4 = id & 31;
            *(float4*)&Xs[row * 128 + c4 * 4] =
                *(const float4*)(Xg + (size_t)(kc * 64 + row) * 1024 + c4 * 4);
        }
        __syncthreads();
        #pragma unroll 8
        for (int k = 0; k < 64; k++) {
            ull x0 = *(const ull*)&Xs[k * 128 + tx * 4];
            ull x1 = *(const ull*)&Xs[k * 128 + tx * 4 + 2];
            #pragma unroll
            for (int r = 0; r < 8; r++) {
                ull wv = pk2(Ws[(ty * 8 + r) * 64 + k]);
                fma2(acc[r][0], wv, x0);
                fma2(acc[r][1], wv, x1);
            }
        }
    }
    #pragma unroll
    for (int r = 0; r < 8; r++) {
        int o = ot * 64 + ty * 8 + r;
        float inv = gam[o] * rsqrtf(var[o] + 1e-5f);
        float bs  = bet[o] - mu[o] * inv;
        float2 a = upk(acc[r][0]), c2 = upk(acc[r][1]);
        float4 v;
        v.x = fmaxf(fmaf(a.x,  inv, bs), 0.f);
        v.y = fmaxf(fmaf(a.y,  inv, bs), 0.f);
        v.z = fmaxf(fmaf(c2.x, inv, bs), 0.f);
        v.w = fmaxf(fmaf(c2.y, inv, bs), 0.f);
        *(float4*)&g_FH[((size_t)b * 256 + o) * 1024 + st * 128 + tx * 4] = v;
    }
}

// ==== fc GEMM, transposed store; destination resolved IN DEVICE CODE =======
template<bool TO_KT, int LOGW>
__global__ void __launch_bounds__(256) fcT_k(
    const float* __restrict__ Xin, const float* __restrict__ W,
    const float* __restrict__ bias)
{
    __shared__ float Xs[128 * 64];
    __shared__ float Ws[64 * 66];
    const int t = threadIdx.x, tx = t & 15, ty = t >> 4;
    const int n0 = blockIdx.x * 128;
    const int WW = 1 << LOGW;
    const float* X = TO_KT ? (const float*)g_FH : Xin;
    float* dst = TO_KT ? g_Kt : g_Qt;        // device-side symbol -> valid address

    ull acc[8][2];
    #pragma unroll
    for (int r = 0; r < 8; r++) { acc[r][0] = 0ull; acc[r][1] = 0ull; }

    for (int kc = 0; kc < 4; kc++) {
        __syncthreads();
        #pragma unroll
        for (int i = 0; i < 8; i++) {
            int id = i * 256 + t; int row = id >> 4, c4 = id & 15;
            *(float4*)&Xs[row * 64 + c4 * 4] =
                *(const float4*)(X + (size_t)(n0 + row) * 256 + kc * 64 + c4 * 4);
        }
        #pragma unroll
        for (int i = 0; i < 16; i++) {
            int id = i * 256 + t; int d = id >> 6, c = id & 63;
            Ws[c * 66 + d] = W[(size_t)d * 256 + kc * 64 + c];
        }
        __syncthreads();
        #pragma unroll 8
        for (int c = 0; c < 64; c++) {
            ull w0 = *(const ull*)&Ws[c * 66 + tx * 4];
            ull w1 = *(const ull*)&Ws[c * 66 + tx * 4 + 2];
            #pragma unroll
            for (int r = 0; r < 8; r++) {
                ull xv = pk2(Xs[(ty * 8 + r) * 64 + c]);
                fma2(acc[r][0], xv, w0);
                fma2(acc[r][1], xv, w1);
            }
        }
    }
    float4 bv = *(const float4*)(bias + tx * 4);
    #pragma unroll
    for (int r = 0; r < 8; r++) {
        int n = n0 + ty * 8 + r;
        int bb = n >> LOGW, nn = n & (WW - 1);
        float2 a = upk(acc[r][0]), c2 = upk(acc[r][1]);
        dst[((size_t)bb * 64 + tx * 4 + 0) * WW + nn] = a.x  + bv.x;
        dst[((size_t)bb * 64 + tx * 4 + 1) * WW + nn] = a.y  + bv.y;
        dst[((size_t)bb * 64 + tx * 4 + 2) * WW + nn] = c2.x + bv.z;
        dst[((size_t)bb * 64 + tx * 4 + 3) * WW + nn] = c2.y + bv.w;
    }
}

// ========================== fused attention ================================
// 256 thr / 8 warps, 64 Q-rows x 256 cols, 32 m-chunks of 32, 2 CTAs/SM.
#define Q_O 0
#define K_O 4096
#define F_O 8192
#define S_O 16384
#define T_O 18688
#define A_O 20864
#define I_O 20928
#define SMF 20992

__device__ __forceinline__ void issue_Kt(float* sm, const float* Ktg, int t, int c) {
    #pragma unroll
    for (int i = 0; i < 2; i++) {
        int id = i * 256 + t; int d = id >> 3, ch = id & 7;
        cp16(cvta_s(sm + K_O + (c & 1) * 2048 + d * 32 + ch * 4),
             Ktg + (size_t)d * 1024 + c * 32 + ch * 4);
    }
}
__device__ __forceinline__ void issue_FH(float* sm, const float* FHg, int t, int c) {
    #pragma unroll
    for (int i = 0; i < 8; i++) {
        int id = i * 256 + t; int m = id >> 6, ch = id & 63;
        cp16(cvta_s(sm + F_O + m * 256 + ch * 4),
             FHg + (size_t)(c * 32 + m) * 256 + ch * 4);
    }
}

__global__ void __launch_bounds__(256, 2) attn_k(
    const float* __restrict__ scp, float* __restrict__ out)
{
    extern __shared__ float sm[];
    const int b = blockIdx.y, nblk = blockIdx.x;
    const int t = threadIdx.x, w = t >> 5, l = t & 31;
    const int wr = w & 1, wc = w >> 1;
    const int rg = l >> 3, cg = l & 7;
    const int R0 = 32 * wr + 8 * rg, C0 = 64 * wc + 8 * cg;
    const int g2 = w >> 1, sl2 = w & 1;
    const int riS = l >> 2, cpS = l & 3;
    const int srow = 8 * w + (l >> 2), ms = l & 3;

    const float* Qtg = g_Qt + (size_t)b * 64 * 4096 + nblk * 64;
    const float* Ktg = g_Kt + (size_t)b * 64 * 1024;
    const float* FHg = g_FH + (size_t)b * 1024 * 256;

    #pragma unroll
    for (int i = 0; i < 4; i++) {
        int id = i * 256 + t; int d = id >> 4, ch = id & 15;
        cp16(cvta_s(sm + Q_O + d * 64 + ch * 4), Qtg + (size_t)d * 4096 + ch * 4);
    }
    issue_Kt(sm, Ktg, t, 0);
    cp_commit();

    ull o[8][4];
    #pragma unroll
    for (int i = 0; i < 8; i++)
        #pragma unroll
        for (int j = 0; j < 4; j++) o[i][j] = 0ull;
    float mrun = -INFINITY, lrun = 0.f;

    for (int c = 0; c < 32; c++) {
        issue_FH(sm, FHg, t, c);
        cp_commit();
        if (c < 31) { issue_Kt(sm, Ktg, t, c + 1); cp_commit(); cp_wait<2>(); }
        else        { cp_wait<1>(); }
        __syncthreads();

        // ---- S ----
        {
            const float* Kb = sm + K_O + (c & 1) * 2048 + 16 * sl2 + 4 * cpS;
            const float* qp = sm + Q_O + 16 * g2 + riS;
            ull s00 = 0ull, s01 = 0ull, s10 = 0ull, s11 = 0ull;
            #pragma unroll 8
            for (int d = 0; d < 64; d++) {
                ull kx = *(const ull*)(Kb + d * 32);
                ull ky = *(const ull*)(Kb + d * 32 + 2);
                ull q0 = pk2(qp[d * 64]);
                ull q1 = pk2(qp[d * 64 + 8]);
                fma2(s00, q0, kx); fma2(s01, q0, ky);
                fma2(s10, q1, kx); fma2(s11, q1, ky);
            }
            float* sp0 = sm + S_O + (16 * g2 + riS) * 36 + 16 * sl2 + 4 * cpS;
            *(ull*)sp0 = s00; *(ull*)(sp0 + 2) = s01;
            float* sp1 = sp0 + 8 * 36;
            *(ull*)sp1 = s10; *(ull*)(sp1 + 2) = s11;
        }
        __syncthreads();

        // ---- softmax (lane quad per row; 8 m per lane) ----
        {
            const float* sr = sm + S_O + srow * 36 + ms * 8;
            float4 a  = *(const float4*)sr;
            float4 b4 = *(const float4*)(sr + 4);
            float mt = fmaxf(fmaxf(fmaxf(a.x, a.y), fmaxf(a.z, a.w)),
                             fmaxf(fmaxf(b4.x, b4.y), fmaxf(b4.z, b4.w)));
            mt = fmaxf(mt, __shfl_xor_sync(0xffffffffu, mt, 1));
            mt = fmaxf(mt, __shfl_xor_sync(0xffffffffu, mt, 2));
            float mnew  = fmaxf(mrun, mt);
            float alpha = __expf(mrun - mnew);
            float e0 = __expf(a.x  - mnew), e1 = __expf(a.y  - mnew);
            float e2 = __expf(a.z  - mnew), e3 = __expf(a.w  - mnew);
            float e4 = __expf(b4.x - mnew), e5 = __expf(b4.y - mnew);
            float e6 = __expf(b4.z - mnew), e7 = __expf(b4.w - mnew);
            float ps = ((e0 + e1) + (e2 + e3)) + ((e4 + e5) + (e6 + e7));
            ps += __shfl_xor_sync(0xffffffffu, ps, 1);
            ps += __shfl_xor_sync(0xffffffffu, ps, 2);
            lrun = lrun * alpha + ps;
            mrun = mnew;
            if (ms == 0) sm[A_O + srow] = alpha;
            float* pp = sm + T_O + (ms * 8) * 68 + (srow ^ (8 * ms));
            pp[0 * 68] = e0; pp[1 * 68] = e1; pp[2 * 68] = e2; pp[3 * 68] = e3;
            pp[4 * 68] = e4; pp[5 * 68] = e5; pp[6 * 68] = e6; pp[7 * 68] = e7;
        }
        if (c < 31) cp_wait<1>(); else cp_wait<0>();
        __syncthreads();

        // ---- PV ----
        {
            #pragma unroll
            for (int i = 0; i < 8; i++) {
                ull a2 = pk2(sm[A_O + R0 + i]);
                o[i][0] = mul2(o[i][0], a2); o[i][1] = mul2(o[i][1], a2);
                o[i][2] = mul2(o[i][2], a2); o[i][3] = mul2(o[i][3], a2);
            }
            const float* Fb = sm + F_O + C0;
            const float* Pb = sm + T_O;
            #pragma unroll 2
            for (int m = 0; m < 32; m++) {
                int rsw = R0 ^ (8 * (m >> 3));
                float4 pa = *(const float4*)(Pb + m * 68 + rsw);
                float4 pb = *(const float4*)(Pb + m * 68 + rsw + 4);
                const float* fr = Fb + m * 256;
                ull f0 = *(const ull*)fr,       f1 = *(const ull*)(fr + 2);
                ull f2 = *(const ull*)(fr + 4), f3 = *(const ull*)(fr + 6);
                ull p;
                p = pk2(pa.x); fma2(o[0][0],p,f0); fma2(o[0][1],p,f1); fma2(o[0][2],p,f2); fma2(o[0][3],p,f3);
                p = pk2(pa.y); fma2(o[1][0],p,f0); fma2(o[1][1],p,f1); fma2(o[1][2],p,f2); fma2(o[1][3],p,f3);
                p = pk2(pa.z); fma2(o[2][0],p,f0); fma2(o[2][1],p,f1); fma2(o[2][2],p,f2); fma2(o[2][3],p,f3);
                p = pk2(pa.w); fma2(o[3][0],p,f0); fma2(o[3][1],p,f1); fma2(o[3][2],p,f2); fma2(o[3][3],p,f3);
                p = pk2(pb.x); fma2(o[4][0],p,f0); fma2(o[4][1],p,f1); fma2(o[4][2],p,f2); fma2(o[4][3],p,f3);
                p = pk2(pb.y); fma2(o[5][0],p,f0); fma2(o[5][1],p,f1); fma2(o[5][2],p,f2); fma2(o[5][3],p,f3);
                p = pk2(pb.z); fma2(o[6][0],p,f0); fma2(o[6][1],p,f1); fma2(o[6][2],p,f2); fma2(o[6][3],p,f3);
                p = pk2(pb.w); fma2(o[7][0],p,f0); fma2(o[7][1],p,f1); fma2(o[7][2],p,f2); fma2(o[7][3],p,f3);
            }
        }
        __syncthreads();
    }

    // ---- epilogue ----
    if (ms == 0) sm[I_O + srow] = scp[0] / lrun;
    __syncthreads();
    #pragma unroll
    for (int i = 0; i < 8; i++) {
        ull a2 = pk2(sm[I_O + R0 + i]);
        o[i][0] = mul2(o[i][0], a2); o[i][1] = mul2(o[i][1], a2);
        o[i][2] = mul2(o[i][2], a2); o[i][3] = mul2(o[i][3], a2);
    }
    float* stg = sm + F_O;                         // 32x257 staging (S region dead)
    float* outB = out + (size_t)b * 256 * 4096 + nblk * 64;
    for (int p = 0; p < 2; p++) {
        __syncthreads();
        if (wr == p) {
            #pragma unroll
            for (int i = 0; i < 8; i++)
                #pragma unroll
                for (int j = 0; j < 4; j++) {
                    float2 v = upk(o[i][j]);
                    stg[(8 * rg + i) * 257 + C0 + 2 * j]     = v.x;
                    stg[(8 * rg + i) * 257 + C0 + 2 * j + 1] = v.y;
                }
        }
        __syncthreads();
        #pragma unroll
        for (int k2 = 0; k2 < 8; k2++) {
            int idx = k2 * 256 + t;
            int ch = idx >> 3, ns = idx & 7;
            float4 v;
            v.x = stg[(ns * 4 + 0) * 257 + ch];
            v.y = stg[(ns * 4 + 1) * 257 + ch];
            v.z = stg[(ns * 4 + 2) * 257 + ch];
            v.w = stg[(ns * 4 + 3) * 257 + ch];
            *(float4*)(outB + (size_t)ch * 4096 + p * 32 + ns * 4) = v;
        }
    }
}

extern "C" void kernel_launch(void* const* d_in, const int* in_sizes, int n_in,
                              void* d_out, int out_size)
{
    conv_k<<<dim3(8, 4, 8), 256>>>((const float*)d_in[1], (const float*)d_in[2],
        (const float*)d_in[3], (const float*)d_in[4],
        (const float*)d_in[5], (const float*)d_in[6]);
    fcT_k<false, 12><<<256, 256>>>((const float*)d_in[0], (const float*)d_in[7],
                                   (const float*)d_in[8]);
    fcT_k<true,  10><<<64,  256>>>(nullptr, (const float*)d_in[9],
                                   (const float*)d_in[10]);
    cudaFuncSetAttribute(attn_k, cudaFuncAttributeMaxDynamicSharedMemorySize, SMF * 4);
    attn_k<<<dim3(64, 8), 256, SMF * 4>>>((const float*)d_in[11], (float*)d_out);
}

// round 11
// speedup vs baseline: 1.4289x; 1.0014x over previous
#include <cuda_runtime.h>
#include <math.h>
#include <stdint.h>

typedef unsigned long long ull;

__device__ float g_FH[8 * 1024 * 256];   // [b][m][c] (flat reshape of conv out)
__device__ float g_Qt[8 * 64 * 4096];    // [b][d][n]
__device__ float g_Kt[8 * 64 * 1024];    // [b][d][m]

__device__ __forceinline__ void fma2(ull &d, ull a, ull b) {
    asm("fma.rn.f32x2 %0, %1, %2, %0;" : "+l"(d) : "l"(a), "l"(b));
}
__device__ __forceinline__ ull mul2(ull a, ull b) {
    ull r; asm("mul.rn.f32x2 %0, %1, %2;" : "=l"(r) : "l"(a), "l"(b)); return r;
}
__device__ __forceinline__ ull pk2(float x) {
    ull r; asm("mov.b64 %0, {%1, %1};" : "=l"(r) : "r"(__float_as_uint(x))); return r;
}
__device__ __forceinline__ float2 upk(ull v) {
    float2 f; asm("mov.b64 {%0, %1}, %2;" : "=f"(f.x), "=f"(f.y) : "l"(v)); return f;
}
__device__ __forceinline__ uint32_t cvta_s(const void* p) {
    return (uint32_t)__cvta_generic_to_shared(p);
}
__device__ __forceinline__ void cp16(uint32_t dst, const void* src) {
    asm volatile("cp.async.cg.shared.global [%0], [%1], 16;\n" :: "r"(dst), "l"(src) : "memory");
}
__device__ __forceinline__ void cp_commit() {
    asm volatile("cp.async.commit_group;\n" ::: "memory");
}
template<int N> __device__ __forceinline__ void cp_wait() {
    asm volatile("cp.async.wait_group %0;\n" :: "n"(N) : "memory");
}

// ======================= conv+BN+ReLU (proven) =============================
__global__ void __launch_bounds__(256) conv_k(
    const float* __restrict__ FHin, const float* __restrict__ Wc,
    const float* __restrict__ gam, const float* __restrict__ bet,
    const float* __restrict__ mu,  const float* __restrict__ var)
{
    __shared__ float Ws[64 * 64];
    __shared__ float Xs[64 * 128];
    const int t = threadIdx.x, tx = t & 31, ty = t >> 5;
    const int st = blockIdx.x, ot = blockIdx.y, b = blockIdx.z;
    const float* Xg = FHin + (size_t)b * 512 * 1024 + st * 128;
    const float* Wg = Wc + (size_t)ot * 64 * 512;

    ull acc[8][2];
    #pragma unroll
    for (int r = 0; r < 8; r++) { acc[r][0] = 0ull; acc[r][1] = 0ull; }

    for (int kc = 0; kc < 8; kc++) {
        __syncthreads();
        #pragma unroll
        for (int i = 0; i < 16; i++) {
            int id = i * 256 + t; int row = id >> 6, col = id & 63;
            Ws[row * 64 + col] = Wg[(size_t)row * 512 + kc * 64 + col];
        }
        #pragma unroll
        for (int i = 0; i < 8; i++) {
            int id = i * 256 + t; int row = id >> 5, c4 = id & 31;
            *(float4*)&Xs[row * 128 + c4 * 4] =
                *(const float4*)(Xg + (size_t)(kc * 64 + row) * 1024 + c4 * 4);
        }
        __syncthreads();
        #pragma unroll 8
        for (int k = 0; k < 64; k++) {
            ull x0 = *(const ull*)&Xs[k * 128 + tx * 4];
            ull x1 = *(const ull*)&Xs[k * 128 + tx * 4 + 2];
            #pragma unroll
            for (int r = 0; r < 8; r++) {
                ull wv = pk2(Ws[(ty * 8 + r) * 64 + k]);
                fma2(acc[r][0], wv, x0);
                fma2(acc[r][1], wv, x1);
            }
        }
    }
    #pragma unroll
    for (int r = 0; r < 8; r++) {
        int o = ot * 64 + ty * 8 + r;
        float inv = gam[o] * rsqrtf(var[o] + 1e-5f);
        float bs  = bet[o] - mu[o] * inv;
        float2 a = upk(acc[r][0]), c2 = upk(acc[r][1]);
        float4 v;
        v.x = fmaxf(fmaf(a.x,  inv, bs), 0.f);
        v.y = fmaxf(fmaf(a.y,  inv, bs), 0.f);
        v.z = fmaxf(fmaf(c2.x, inv, bs), 0.f);
        v.w = fmaxf(fmaf(c2.y, inv, bs), 0.f);
        *(float4*)&g_FH[((size_t)b * 256 + o) * 1024 + st * 128 + tx * 4] = v;
    }
}

// ==== fc GEMM, transposed store; destination resolved IN DEVICE CODE =======
template<bool TO_KT, int LOGW>
__global__ void __launch_bounds__(256) fcT_k(
    const float* __restrict__ Xin, const float* __restrict__ W,
    const float* __restrict__ bias)
{
    __shared__ float Xs[128 * 64];
    __shared__ float Ws[64 * 66];
    const int t = threadIdx.x, tx = t & 15, ty = t >> 4;
    const int n0 = blockIdx.x * 128;
    const int WW = 1 << LOGW;
    const float* X = TO_KT ? (const float*)g_FH : Xin;
    float* dst = TO_KT ? g_Kt : g_Qt;        // device-side symbol -> valid address

    ull acc[8][2];
    #pragma unroll
    for (int r = 0; r < 8; r++) { acc[r][0] = 0ull; acc[r][1] = 0ull; }

    for (int kc = 0; kc < 4; kc++) {
        __syncthreads();
        #pragma unroll
        for (int i = 0; i < 8; i++) {
            int id = i * 256 + t; int row = id >> 4, c4 = id & 15;
            *(float4*)&Xs[row * 64 + c4 * 4] =
                *(const float4*)(X + (size_t)(n0 + row) * 256 + kc * 64 + c4 * 4);
        }
        #pragma unroll
        for (int i = 0; i < 16; i++) {
            int id = i * 256 + t; int d = id >> 6, c = id & 63;
            Ws[c * 66 + d] = W[(size_t)d * 256 + kc * 64 + c];
        }
        __syncthreads();
        #pragma unroll 8
        for (int c = 0; c < 64; c++) {
            ull w0 = *(const ull*)&Ws[c * 66 + tx * 4];
            ull w1 = *(const ull*)&Ws[c * 66 + tx * 4 + 2];
            #pragma unroll
            for (int r = 0; r < 8; r++) {
                ull xv = pk2(Xs[(ty * 8 + r) * 64 + c]);
                fma2(acc[r][0], xv, w0);
                fma2(acc[r][1], xv, w1);
            }
        }
    }
    float4 bv = *(const float4*)(bias + tx * 4);
    #pragma unroll
    for (int r = 0; r < 8; r++) {
        int n = n0 + ty * 8 + r;
        int bb = n >> LOGW, nn = n & (WW - 1);
        float2 a = upk(acc[r][0]), c2 = upk(acc[r][1]);
        dst[((size_t)bb * 64 + tx * 4 + 0) * WW + nn] = a.x  + bv.x;
        dst[((size_t)bb * 64 + tx * 4 + 1) * WW + nn] = a.y  + bv.y;
        dst[((size_t)bb * 64 + tx * 4 + 2) * WW + nn] = c2.x + bv.z;
        dst[((size_t)bb * 64 + tx * 4 + 3) * WW + nn] = c2.y + bv.w;
    }
}

// ========================== fused attention ================================
// 256 thr / 8 warps, 64 Q-rows x 256 cols, 32 m-chunks of 32, 2 CTAs/SM.
#define Q_O 0
#define K_O 4096
#define F_O 8192
#define S_O 16384
#define T_O 18688
#define A_O 20864
#define I_O 20928
#define SMF 20992

__device__ __forceinline__ void issue_Kt(float* sm, const float* Ktg, int t, int c) {
    #pragma unroll
    for (int i = 0; i < 2; i++) {
        int id = i * 256 + t; int d = id >> 3, ch = id & 7;
        cp16(cvta_s(sm + K_O + (c & 1) * 2048 + d * 32 + ch * 4),
             Ktg + (size_t)d * 1024 + c * 32 + ch * 4);
    }
}
__device__ __forceinline__ void issue_FH(float* sm, const float* FHg, int t, int c) {
    #pragma unroll
    for (int i = 0; i < 8; i++) {
        int id = i * 256 + t; int m = id >> 6, ch = id & 63;
        cp16(cvta_s(sm + F_O + m * 256 + ch * 4),
             FHg + (size_t)(c * 32 + m) * 256 + ch * 4);
    }
}

__global__ void __launch_bounds__(256, 2) attn_k(
    const float* __restrict__ scp, float* __restrict__ out)
{
    extern __shared__ float sm[];
    const int b = blockIdx.y, nblk = blockIdx.x;
    const int t = threadIdx.x, w = t >> 5, l = t & 31;
    const int wr = w & 1, wc = w >> 1;
    const int rg = l >> 3, cg = l & 7;
    const int R0 = 32 * wr + 8 * rg, C0 = 64 * wc + 8 * cg;
    const int g2 = w >> 1, sl2 = w & 1;
    const int riS = l >> 2, cpS = l & 3;
    const int srow = 8 * w + (l >> 2), ms = l & 3;

    const float* Qtg = g_Qt + (size_t)b * 64 * 4096 + nblk * 64;
    const float* Ktg = g_Kt + (size_t)b * 64 * 1024;
    const float* FHg = g_FH + (size_t)b * 1024 * 256;

    #pragma unroll
    for (int i = 0; i < 4; i++) {
        int id = i * 256 + t; int d = id >> 4, ch = id & 15;
        cp16(cvta_s(sm + Q_O + d * 64 + ch * 4), Qtg + (size_t)d * 4096 + ch * 4);
    }
    issue_Kt(sm, Ktg, t, 0);
    cp_commit();

    ull o[8][4];
    #pragma unroll
    for (int i = 0; i < 8; i++)
        #pragma unroll
        for (int j = 0; j < 4; j++) o[i][j] = 0ull;
    float mrun = -INFINITY, lrun = 0.f;

    for (int c = 0; c < 32; c++) {
        issue_FH(sm, FHg, t, c);
        cp_commit();
        if (c < 31) { issue_Kt(sm, Ktg, t, c + 1); cp_commit(); cp_wait<2>(); }
        else        { cp_wait<1>(); }
        __syncthreads();

        // ---- S ----
        {
            const float* Kb = sm + K_O + (c & 1) * 2048 + 16 * sl2 + 4 * cpS;
            const float* qp = sm + Q_O + 16 * g2 + riS;
            ull s00 = 0ull, s01 = 0ull, s10 = 0ull, s11 = 0ull;
            #pragma unroll 8
            for (int d = 0; d < 64; d++) {
                ull kx = *(const ull*)(Kb + d * 32);
                ull ky = *(const ull*)(Kb + d * 32 + 2);
                ull q0 = pk2(qp[d * 64]);
                ull q1 = pk2(qp[d * 64 + 8]);
                fma2(s00, q0, kx); fma2(s01, q0, ky);
                fma2(s10, q1, kx); fma2(s11, q1, ky);
            }
            float* sp0 = sm + S_O + (16 * g2 + riS) * 36 + 16 * sl2 + 4 * cpS;
            *(ull*)sp0 = s00; *(ull*)(sp0 + 2) = s01;
            float* sp1 = sp0 + 8 * 36;
            *(ull*)sp1 = s10; *(ull*)(sp1 + 2) = s11;
        }
        __syncthreads();

        // ---- softmax (lane quad per row; 8 m per lane) ----
        {
            const float* sr = sm + S_O + srow * 36 + ms * 8;
            float4 a  = *(const float4*)sr;
            float4 b4 = *(const float4*)(sr + 4);
            float mt = fmaxf(fmaxf(fmaxf(a.x, a.y), fmaxf(a.z, a.w)),
                             fmaxf(fmaxf(b4.x, b4.y), fmaxf(b4.z, b4.w)));
            mt = fmaxf(mt, __shfl_xor_sync(0xffffffffu, mt, 1));
            mt = fmaxf(mt, __shfl_xor_sync(0xffffffffu, mt, 2));
            float mnew  = fmaxf(mrun, mt);
            float alpha = __expf(mrun - mnew);
            float e0 = __expf(a.x  - mnew), e1 = __expf(a.y  - mnew);
            float e2 = __expf(a.z  - mnew), e3 = __expf(a.w  - mnew);
            float e4 = __expf(b4.x - mnew), e5 = __expf(b4.y - mnew);
            float e6 = __expf(b4.z - mnew), e7 = __expf(b4.w - mnew);
            float ps = ((e0 + e1) + (e2 + e3)) + ((e4 + e5) + (e6 + e7));
            ps += __shfl_xor_sync(0xffffffffu, ps, 1);
            ps += __shfl_xor_sync(0xffffffffu, ps, 2);
            lrun = lrun * alpha + ps;
            mrun = mnew;
            if (ms == 0) sm[A_O + srow] = alpha;
            float* pp = sm + T_O + (ms * 8) * 68 + (srow ^ (8 * ms));
            pp[0 * 68] = e0; pp[1 * 68] = e1; pp[2 * 68] = e2; pp[3 * 68] = e3;
            pp[4 * 68] = e4; pp[5 * 68] = e5; pp[6 * 68] = e6; pp[7 * 68] = e7;
        }
        if (c < 31) cp_wait<1>(); else cp_wait<0>();
        __syncthreads();

        // ---- PV ----
        {
            #pragma unroll
            for (int i = 0; i < 8; i++) {
                ull a2 = pk2(sm[A_O + R0 + i]);
                o[i][0] = mul2(o[i][0], a2); o[i][1] = mul2(o[i][1], a2);
                o[i][2] = mul2(o[i][2], a2); o[i][3] = mul2(o[i][3], a2);
            }
            const float* Fb = sm + F_O + C0;
            const float* Pb = sm + T_O;
            #pragma unroll 2
            for (int m = 0; m < 32; m++) {
                int rsw = R0 ^ (8 * (m >> 3));
                float4 pa = *(const float4*)(Pb + m * 68 + rsw);
                float4 pb = *(const float4*)(Pb + m * 68 + rsw + 4);
                const float* fr = Fb + m * 256;
                ull f0 = *(const ull*)fr,       f1 = *(const ull*)(fr + 2);
                ull f2 = *(const ull*)(fr + 4), f3 = *(const ull*)(fr + 6);
                ull p;
                p = pk2(pa.x); fma2(o[0][0],p,f0); fma2(o[0][1],p,f1); fma2(o[0][2],p,f2); fma2(o[0][3],p,f3);
                p = pk2(pa.y); fma2(o[1][0],p,f0); fma2(o[1][1],p,f1); fma2(o[1][2],p,f2); fma2(o[1][3],p,f3);
                p = pk2(pa.z); fma2(o[2][0],p,f0); fma2(o[2][1],p,f1); fma2(o[2][2],p,f2); fma2(o[2][3],p,f3);
                p = pk2(pa.w); fma2(o[3][0],p,f0); fma2(o[3][1],p,f1); fma2(o[3][2],p,f2); fma2(o[3][3],p,f3);
                p = pk2(pb.x); fma2(o[4][0],p,f0); fma2(o[4][1],p,f1); fma2(o[4][2],p,f2); fma2(o[4][3],p,f3);
                p = pk2(pb.y); fma2(o[5][0],p,f0); fma2(o[5][1],p,f1); fma2(o[5][2],p,f2); fma2(o[5][3],p,f3);
                p = pk2(pb.z); fma2(o[6][0],p,f0); fma2(o[6][1],p,f1); fma2(o[6][2],p,f2); fma2(o[6][3],p,f3);
                p = pk2(pb.w); fma2(o[7][0],p,f0); fma2(o[7][1],p,f1); fma2(o[7][2],p,f2); fma2(o[7][3],p,f3);
            }
        }
        __syncthreads();
    }

    // ---- epilogue ----
    if (ms == 0) sm[I_O + srow] = scp[0] / lrun;
    __syncthreads();
    #pragma unroll
    for (int i = 0; i < 8; i++) {
        ull a2 = pk2(sm[I_O + R0 + i]);
        o[i][0] = mul2(o[i][0], a2); o[i][1] = mul2(o[i][1], a2);
        o[i][2] = mul2(o[i][2], a2); o[i][3] = mul2(o[i][3], a2);
    }
    float* stg = sm + F_O;                         // 32x257 staging (S region dead)
    float* outB = out + (size_t)b * 256 * 4096 + nblk * 64;
    for (int p = 0; p < 2; p++) {
        __syncthreads();
        if (wr == p) {
            #pragma unroll
            for (int i = 0; i < 8; i++)
                #pragma unroll
                for (int j = 0; j < 4; j++) {
                    float2 v = upk(o[i][j]);
                    stg[(8 * rg + i) * 257 + C0 + 2 * j]     = v.x;
                    stg[(8 * rg + i) * 257 + C0 + 2 * j + 1] = v.y;
                }
        }
        __syncthreads();
        #pragma unroll
        for (int k2 = 0; k2 < 8; k2++) {
            int idx = k2 * 256 + t;
            int ch = idx >> 3, ns = idx & 7;
            float4 v;
            v.x = stg[(ns * 4 + 0) * 257 + ch];
            v.y = stg[(ns * 4 + 1) * 257 + ch];
            v.z = stg[(ns * 4 + 2) * 257 + ch];
            v.w = stg[(ns * 4 + 3) * 257 + ch];
            *(float4*)(outB + (size_t)ch * 4096 + p * 32 + ns * 4) = v;
        }
    }
}

extern "C" void kernel_launch(void* const* d_in, const int* in_sizes, int n_in,
                              void* d_out, int out_size)
{
    conv_k<<<dim3(8, 4, 8), 256>>>((const float*)d_in[1], (const float*)d_in[2],
        (const float*)d_in[3], (const float*)d_in[4],
        (const float*)d_in[5], (const float*)d_in[6]);
    fcT_k<false, 12><<<256, 256>>>((const float*)d_in[0], (const float*)d_in[7],
                                   (const float*)d_in[8]);
    fcT_k<true,  10><<<64,  256>>>(nullptr, (const float*)d_in[9],
                                   (const float*)d_in[10]);
    cudaFuncSetAttribute(attn_k, cudaFuncAttributeMaxDynamicSharedMemorySize, SMF * 4);
    attn_k<<<dim3(64, 8), 256, SMF * 4>>>((const float*)d_in[11], (float*)d_out);
}